// round 1
// baseline (speedup 1.0000x reference)
#include <cuda_runtime.h>
#include <math.h>

#define B_ 2048
#define F_ 128
#define U_ 1024
#define V_ 512
#define C_ 10

// Global scratch (no allocations allowed in kernel_launch)
__device__ float g_logits[B_ * C_];
__device__ float g_bsum[C_];

// ---------------------------------------------------------------------------
// Kernel 0: zero logits accumulator; compute bsum[c] = b_out[c] + sum_f b2[f,c]
// ---------------------------------------------------------------------------
__global__ void nam_init_kernel(const float* __restrict__ b2,
                                const float* __restrict__ b_out) {
    int t = blockIdx.x * blockDim.x + threadIdx.x;
    if (t < B_ * C_) g_logits[t] = 0.0f;
    if (t < C_) {
        float s = b_out[t];
        #pragma unroll 4
        for (int f = 0; f < F_; f++) s += b2[f * C_ + t];
        g_bsum[t] = s;
    }
}

// ---------------------------------------------------------------------------
// Kernel 1: main fused grouped GEMM.
// Grid: (V/128, B/128, F). Block: 256 threads, each computes an 8x8 microtile
// of h2 = relu(h @ W1[f] + b1[f]) where h = clip((x[:,f]-eb)*exp(exu_w[f]),0,1)
// is generated on the fly into smem. Epilogue multiplies by W2[f] (V x 10),
// reduces over the v-tile via warp shuffles, atomically adds into g_logits.
// ---------------------------------------------------------------------------
__global__ void __launch_bounds__(256)
nam_main_kernel(const float* __restrict__ x,
                const float* __restrict__ exu_w,
                const float* __restrict__ exu_b,
                const float* __restrict__ W1,
                const float* __restrict__ b1,
                const float* __restrict__ W2) {
    const int f  = blockIdx.z;
    const int b0 = blockIdx.y * 128;
    const int v0 = blockIdx.x * 128;
    const int tid = threadIdx.x;
    const int tx = tid & 15;   // v-tile sub-block
    const int ty = tid >> 4;   // b-tile sub-block

    __shared__ float ews[U_];          // 4 KB  exp(exu_w[f,:])
    __shared__ float xs[128];          // 0.5KB x[b0+i, f] - exu_b[f]
    __shared__ float As[32][128];      // 16 KB h tile, [k][i]
    __shared__ float Bs[32][128];      // 16 KB W1 tile, [k][j]
    __shared__ float W2s[128][C_];     // 5 KB  W2[f, v0:v0+128, :]

    const float eb = exu_b[f];

    // Precompute exp weights for this feature (once per block)
    for (int u = tid; u < U_; u += 256)
        ews[u] = expf(exu_w[f * U_ + u]);
    if (tid < 128)
        xs[tid] = x[(size_t)(b0 + tid) * F_ + f] - eb;
    // W2 tile
    for (int i = tid; i < 128 * C_; i += 256) {
        int j = i / C_, c = i - j * C_;
        W2s[j][c] = W2[(size_t)f * V_ * C_ + (size_t)(v0 + j) * C_ + c];
    }
    __syncthreads();

    float acc[8][8];
    #pragma unroll
    for (int i = 0; i < 8; i++)
        #pragma unroll
        for (int j = 0; j < 8; j++) acc[i][j] = 0.0f;

    const float* W1f = W1 + (size_t)f * U_ * V_;

    for (int u0 = 0; u0 < U_; u0 += 32) {
        // --- fill Bs: 32x128 floats = 1024 float4, 4 per thread, coalesced ---
        {
            int idx = tid;
            #pragma unroll
            for (int r = 0; r < 4; r++, idx += 256) {
                int k  = idx >> 5;            // 32 float4 per row
                int j4 = (idx & 31) << 2;
                float4 w = *(const float4*)&W1f[(size_t)(u0 + k) * V_ + v0 + j4];
                *(float4*)&Bs[k][j4] = w;
            }
        }
        // --- fill As: h[k][i] = clip(xs[i] * ews[u0+k], 0, 1) ---
        {
            int idx = tid;
            #pragma unroll
            for (int r = 0; r < 4; r++, idx += 256) {
                int k  = idx >> 5;
                int i4 = (idx & 31) << 2;
                float ew = ews[u0 + k];
                float4 h;
                h.x = fminf(fmaxf(xs[i4 + 0] * ew, 0.0f), 1.0f);
                h.y = fminf(fmaxf(xs[i4 + 1] * ew, 0.0f), 1.0f);
                h.z = fminf(fmaxf(xs[i4 + 2] * ew, 0.0f), 1.0f);
                h.w = fminf(fmaxf(xs[i4 + 3] * ew, 0.0f), 1.0f);
                *(float4*)&As[k][i4] = h;
            }
        }
        __syncthreads();

        #pragma unroll
        for (int k = 0; k < 32; k++) {
            float a[8], b[8];
            *(float4*)&a[0] = *(const float4*)&As[k][ty * 4];
            *(float4*)&a[4] = *(const float4*)&As[k][64 + ty * 4];
            *(float4*)&b[0] = *(const float4*)&Bs[k][tx * 4];
            *(float4*)&b[4] = *(const float4*)&Bs[k][64 + tx * 4];
            #pragma unroll
            for (int i = 0; i < 8; i++)
                #pragma unroll
                for (int j = 0; j < 8; j++)
                    acc[i][j] = fmaf(a[i], b[j], acc[i][j]);
        }
        __syncthreads();
    }

    // --- epilogue: bias + relu, multiply by W2 tile, reduce, atomic ---
    const float* b1f = b1 + (size_t)f * V_ + v0;
    float bb[8];
    #pragma unroll
    for (int j = 0; j < 8; j++) {
        int col = (j < 4) ? (tx * 4 + j) : (64 + tx * 4 + j - 4);
        bb[j] = b1f[col];
    }

    #pragma unroll
    for (int i = 0; i < 8; i++) {
        float p[C_];
        #pragma unroll
        for (int c = 0; c < C_; c++) p[c] = 0.0f;
        #pragma unroll
        for (int j = 0; j < 8; j++) {
            int col = (j < 4) ? (tx * 4 + j) : (64 + tx * 4 + j - 4);
            float h2 = fmaxf(acc[i][j] + bb[j], 0.0f);
            #pragma unroll
            for (int c = 0; c < C_; c++)
                p[c] = fmaf(h2, W2s[col][c], p[c]);
        }
        // reduce over tx (lane bits 0..3 within each warp)
        #pragma unroll
        for (int off = 1; off < 16; off <<= 1)
            #pragma unroll
            for (int c = 0; c < C_; c++)
                p[c] += __shfl_xor_sync(0xffffffffu, p[c], off);
        if (tx == 0) {
            int row = b0 + ((i < 4) ? (ty * 4 + i) : (64 + ty * 4 + i - 4));
            #pragma unroll
            for (int c = 0; c < C_; c++)
                atomicAdd(&g_logits[row * C_ + c], p[c]);
        }
    }
}

// ---------------------------------------------------------------------------
// Kernel 2: add bias-sum, softmax over C=10, write output.
// ---------------------------------------------------------------------------
__global__ void nam_softmax_kernel(float* __restrict__ out) {
    int b = blockIdx.x * blockDim.x + threadIdx.x;
    if (b >= B_) return;
    float v[C_];
    float m = -1e30f;
    #pragma unroll
    for (int c = 0; c < C_; c++) {
        v[c] = g_logits[b * C_ + c] + g_bsum[c];
        m = fmaxf(m, v[c]);
    }
    float s = 0.0f;
    #pragma unroll
    for (int c = 0; c < C_; c++) {
        v[c] = expf(v[c] - m);
        s += v[c];
    }
    float inv = 1.0f / s;
    #pragma unroll
    for (int c = 0; c < C_; c++)
        out[b * C_ + c] = v[c] * inv;
}

// ---------------------------------------------------------------------------
extern "C" void kernel_launch(void* const* d_in, const int* in_sizes, int n_in,
                              void* d_out, int out_size) {
    const float* x     = (const float*)d_in[0];
    const float* exu_w = (const float*)d_in[1];
    const float* exu_b = (const float*)d_in[2];
    const float* W1    = (const float*)d_in[3];
    const float* b1    = (const float*)d_in[4];
    const float* W2    = (const float*)d_in[5];
    const float* b2    = (const float*)d_in[6];
    const float* b_out = (const float*)d_in[7];
    float* out = (float*)d_out;

    nam_init_kernel<<<(B_ * C_ + 255) / 256, 256>>>(b2, b_out);

    dim3 grid(V_ / 128, B_ / 128, F_);
    nam_main_kernel<<<grid, 256>>>(x, exu_w, exu_b, W1, b1, W2);

    nam_softmax_kernel<<<(B_ + 255) / 256, 256>>>(out);
}

// round 3
// speedup vs baseline: 3.7474x; 3.7474x over previous
#include <cuda_runtime.h>
#include <math.h>
#include <stdint.h>

#define B_ 2048
#define F_ 128
#define U_ 1024
#define V_ 512
#define C_ 10

#define BT_ 128            // batch rows per CTA (M)
#define VT_ 256            // v cols per CTA (N)
#define KC_ 32             // k per chunk
#define NCHUNK (U_ / KC_)  // 32
#define STAGES 4

// ---------------- global scratch ----------------
__device__ float g_logits[B_ * C_];
__device__ float g_bsum[C_];
__device__ float g_W1R[(size_t)F_ * U_ * V_];   // tf32(rna)-rounded W1, same layout

// ---------------- helpers ----------------
__device__ __forceinline__ uint32_t smem_u32(const void* p) {
    uint32_t a;
    asm("{ .reg .u64 t; cvta.to.shared.u64 t, %1; cvt.u32.u64 %0, t; }" : "=r"(a) : "l"(p));
    return a;
}
__device__ __forceinline__ void cpa16(uint32_t dst, const void* src) {
    asm volatile("cp.async.cg.shared.global [%0], [%1], 16;" :: "r"(dst), "l"(src));
}
#define CP_COMMIT() asm volatile("cp.async.commit_group;")
#define CP_WAIT(n)  asm volatile("cp.async.wait_group %0;" :: "n"(n))

__device__ __forceinline__ uint32_t tf32_rna_u(float v) {
    uint32_t o;
    asm("cvt.rna.tf32.f32 %0, %1;" : "=r"(o) : "f"(v));
    return o;
}
__device__ __forceinline__ void mma_tf32(float* d, uint32_t a0, uint32_t a1, uint32_t a2,
                                         uint32_t a3, uint32_t b0, uint32_t b1) {
    asm volatile(
        "mma.sync.aligned.m16n8k8.row.col.f32.tf32.tf32.f32 "
        "{%0,%1,%2,%3}, {%4,%5,%6,%7}, {%8,%9}, {%0,%1,%2,%3};"
        : "+f"(d[0]), "+f"(d[1]), "+f"(d[2]), "+f"(d[3])
        : "r"(a0), "r"(a1), "r"(a2), "r"(a3), "r"(b0), "r"(b1));
}

// ---------------- smem layout (dynamic) ----------------
#define STAGE_F (KC_ * VT_)                 // 8192 floats = 32KB
#define STAGES_F (STAGES * STAGE_F)         // 32768 floats
#define EWS_OFF  STAGES_F                   // 1024 floats
#define XS_OFF   (EWS_OFF + U_)             // 128 floats
#define B1S_OFF  (XS_OFF + BT_)             // 256 floats
#define W2S_OFF  (B1S_OFF + VT_)            // 256*12 floats
#define SMEM_FLOATS (W2S_OFF + VT_ * 12)
#define SMEM_BYTES  (SMEM_FLOATS * 4)       // 148992 B

// ---------------------------------------------------------------------------
// Prep: round W1 to tf32 (rna) -> g_W1R. 16384 blocks x 256 thr x 4 float4.
// ---------------------------------------------------------------------------
__global__ void __launch_bounds__(256)
nam_prep_kernel(const float* __restrict__ W1) {
    size_t base = (size_t)blockIdx.x * 1024 + threadIdx.x;
    const float4* src = (const float4*)W1;
    float4* dst = (float4*)g_W1R;
    #pragma unroll
    for (int k = 0; k < 4; k++) {
        size_t i = base + (size_t)k * 256;
        float4 w = src[i];
        float4 o;
        o.x = __uint_as_float(tf32_rna_u(w.x));
        o.y = __uint_as_float(tf32_rna_u(w.y));
        o.z = __uint_as_float(tf32_rna_u(w.z));
        o.w = __uint_as_float(tf32_rna_u(w.w));
        dst[i] = o;
    }
}

// ---------------------------------------------------------------------------
// Init: zero logits; bsum[c] = b_out[c] + sum_f b2[f,c]
// ---------------------------------------------------------------------------
__global__ void nam_init_kernel(const float* __restrict__ b2,
                                const float* __restrict__ b_out) {
    int t = blockIdx.x * blockDim.x + threadIdx.x;
    if (t < B_ * C_) g_logits[t] = 0.0f;
    if (t < C_) {
        float s = b_out[t];
        for (int f = 0; f < F_; f++) s += b2[f * C_ + t];
        g_bsum[t] = s;
    }
}

// ---------------------------------------------------------------------------
// Main: mma.sync tf32 grouped GEMM + fused epilogue.
// Grid (B/128=16, V/256=2, F=128), 256 threads (8 warps, warp tile 64x64).
// ---------------------------------------------------------------------------
__global__ void __launch_bounds__(256, 1)
nam_gemm_kernel(const float* __restrict__ x,
                const float* __restrict__ exu_w,
                const float* __restrict__ exu_b,
                const float* __restrict__ b1,
                const float* __restrict__ W2) {
    extern __shared__ float sm[];
    float* Bs  = sm;                 // STAGES x 8192
    float* ews = sm + EWS_OFF;
    float* xs  = sm + XS_OFF;
    float* b1s = sm + B1S_OFF;
    float* W2s = sm + W2S_OFF;
    float* s_part = sm;              // reuse stage area post-mainloop: [128][4][10]

    const int f  = blockIdx.z;
    const int b0 = blockIdx.x * BT_;
    const int v0 = blockIdx.y * VT_;
    const int tid = threadIdx.x;
    const int wid = tid >> 5;
    const int lane = tid & 31;
    const int g = lane >> 2;         // 0..7
    const int t = lane & 3;          // 0..3
    const int m0 = (wid >> 2) * 64;  // warp M offset
    const int nw = wid & 3;          // warp N index
    const int n0 = nw * 64;          // warp N offset

    const uint32_t smem_base = smem_u32(sm);
    const float* W1f = g_W1R + (size_t)f * U_ * V_ + v0;

    // prologue: kick off first 3 chunk loads (B tile: 32 u-rows x 256 v)
    #pragma unroll
    for (int pc = 0; pc < STAGES - 1; pc++) {
        uint32_t stage = smem_base + (uint32_t)(pc * STAGE_F) * 4u;
        #pragma unroll
        for (int it = 0; it < 8; it++) {
            int i = tid + it * 256;          // 2048 x 16B
            int u = i >> 6;
            int v4 = (i & 63) << 2;
            int vs = v4 ^ ((u & 3) << 3);    // swizzle
            cpa16(stage + (uint32_t)(u * VT_ + vs) * 4u,
                  W1f + (size_t)(pc * KC_ + u) * V_ + v4);
        }
        CP_COMMIT();
    }

    // per-CTA smem fills (overlap with cp.async in flight)
    const float eb = exu_b[f];
    for (int u = tid; u < U_; u += 256) ews[u] = expf(exu_w[f * U_ + u]);
    if (tid < BT_) xs[tid] = x[(size_t)(b0 + tid) * F_ + f] - eb;
    b1s[tid] = b1[(size_t)f * V_ + v0 + tid];
    for (int i = tid; i < VT_ * C_; i += 256) {
        int v = i / C_, c = i - v * C_;
        W2s[v * 12 + c] = W2[(size_t)f * V_ * C_ + (size_t)(v0 + v) * C_ + c];
    }
    __syncthreads();

    // per-lane x values (8 rows this lane touches)
    float xr[4][2];
    #pragma unroll
    for (int mt = 0; mt < 4; mt++) {
        xr[mt][0] = xs[m0 + mt * 16 + g];
        xr[mt][1] = xs[m0 + mt * 16 + g + 8];
    }

    float acc[4][8][4];
    #pragma unroll
    for (int mt = 0; mt < 4; mt++)
        #pragma unroll
        for (int nt = 0; nt < 8; nt++)
            #pragma unroll
            for (int c = 0; c < 4; c++) acc[mt][nt][c] = 0.0f;

    // ---------------- mainloop ----------------
    for (int ch = 0; ch < NCHUNK; ch++) {
        CP_WAIT(2);
        __syncthreads();
        const float* Bst = Bs + (ch & 3) * STAGE_F;

        #pragma unroll
        for (int k8 = 0; k8 < 4; k8++) {
            float e0 = ews[ch * KC_ + k8 * 8 + t];
            float e1 = ews[ch * KC_ + k8 * 8 + 4 + t];
            uint32_t a[4][4];
            #pragma unroll
            for (int mt = 0; mt < 4; mt++) {
                a[mt][0] = tf32_rna_u(__saturatef(xr[mt][0] * e0));
                a[mt][1] = tf32_rna_u(__saturatef(xr[mt][1] * e0));
                a[mt][2] = tf32_rna_u(__saturatef(xr[mt][0] * e1));
                a[mt][3] = tf32_rna_u(__saturatef(xr[mt][1] * e1));
            }
            const int ub = k8 * 8 + t;
            const int sw = t << 3;
            #pragma unroll
            for (int nt = 0; nt < 8; nt++) {
                int v = n0 + nt * 8 + g;
                uint32_t bb0 = __float_as_uint(Bst[ub * VT_ + (v ^ sw)]);
                uint32_t bb1 = __float_as_uint(Bst[(ub + 4) * VT_ + (v ^ sw)]);
                #pragma unroll
                for (int mt = 0; mt < 4; mt++)
                    mma_tf32(acc[mt][nt], a[mt][0], a[mt][1], a[mt][2], a[mt][3], bb0, bb1);
            }
        }

        // issue chunk ch+3
        int nc = ch + STAGES - 1;
        if (nc < NCHUNK) {
            uint32_t stage = smem_base + (uint32_t)((nc & 3) * STAGE_F) * 4u;
            #pragma unroll
            for (int it = 0; it < 8; it++) {
                int i = tid + it * 256;
                int u = i >> 6;
                int v4 = (i & 63) << 2;
                int vs = v4 ^ ((u & 3) << 3);
                cpa16(stage + (uint32_t)(u * VT_ + vs) * 4u,
                      W1f + (size_t)(nc * KC_ + u) * V_ + v4);
            }
            CP_COMMIT();
        }
    }
    __syncthreads();   // mainloop fully done; safe to reuse stage smem as s_part

    // ---------------- epilogue: bias+relu, xW2, reduce ----------------
    #pragma unroll
    for (int pass = 0; pass < 2; pass++) {
        float p[4][10];
        #pragma unroll
        for (int i = 0; i < 4; i++)
            #pragma unroll
            for (int c = 0; c < 10; c++) p[i][c] = 0.0f;

        #pragma unroll
        for (int nt = 0; nt < 8; nt++) {
            #pragma unroll
            for (int k = 0; k < 2; k++) {
                int vl = n0 + nt * 8 + 2 * t + k;
                float b1v = b1s[vl];
                float w2[10];
                #pragma unroll
                for (int c = 0; c < 10; c++) w2[c] = W2s[vl * 12 + c];
                #pragma unroll
                for (int m2 = 0; m2 < 2; m2++) {
                    int mt = pass * 2 + m2;
                    float h2a = fmaxf(acc[mt][nt][k] + b1v, 0.0f);
                    float h2b = fmaxf(acc[mt][nt][2 + k] + b1v, 0.0f);
                    #pragma unroll
                    for (int c = 0; c < 10; c++) {
                        p[m2 * 2 + 0][c] = fmaf(h2a, w2[c], p[m2 * 2 + 0][c]);
                        p[m2 * 2 + 1][c] = fmaf(h2b, w2[c], p[m2 * 2 + 1][c]);
                    }
                }
            }
        }
        // reduce across the quad (lane&3)
        #pragma unroll
        for (int off = 1; off < 4; off <<= 1)
            #pragma unroll
            for (int i = 0; i < 4; i++)
                #pragma unroll
                for (int c = 0; c < 10; c++)
                    p[i][c] += __shfl_xor_sync(0xffffffffu, p[i][c], off);

        if (t == 0) {
            #pragma unroll
            for (int m2 = 0; m2 < 2; m2++)
                #pragma unroll
                for (int rh = 0; rh < 2; rh++) {
                    int r = m0 + (pass * 2 + m2) * 16 + g + rh * 8;  // 0..127
                    #pragma unroll
                    for (int c = 0; c < 10; c++)
                        s_part[(r * 4 + nw) * 10 + c] = p[m2 * 2 + rh][c];
                }
        }
    }
    __syncthreads();

    // combine 4 N-warps, one atomic per (row, class)
    for (int i = tid; i < BT_ * C_; i += 256) {
        int r = i / C_, c = i - r * C_;
        float s = s_part[(r * 4 + 0) * 10 + c] + s_part[(r * 4 + 1) * 10 + c] +
                  s_part[(r * 4 + 2) * 10 + c] + s_part[(r * 4 + 3) * 10 + c];
        atomicAdd(&g_logits[(b0 + r) * C_ + c], s);
    }
}

// ---------------------------------------------------------------------------
// Softmax
// ---------------------------------------------------------------------------
__global__ void nam_softmax_kernel(float* __restrict__ out) {
    int b = blockIdx.x * blockDim.x + threadIdx.x;
    if (b >= B_) return;
    float v[C_];
    float m = -1e30f;
    #pragma unroll
    for (int c = 0; c < C_; c++) {
        v[c] = g_logits[b * C_ + c] + g_bsum[c];
        m = fmaxf(m, v[c]);
    }
    float s = 0.0f;
    #pragma unroll
    for (int c = 0; c < C_; c++) { v[c] = expf(v[c] - m); s += v[c]; }
    float inv = 1.0f / s;
    #pragma unroll
    for (int c = 0; c < C_; c++) out[b * C_ + c] = v[c] * inv;
}

// ---------------------------------------------------------------------------
extern "C" void kernel_launch(void* const* d_in, const int* in_sizes, int n_in,
                              void* d_out, int out_size) {
    const float* x     = (const float*)d_in[0];
    const float* exu_w = (const float*)d_in[1];
    const float* exu_b = (const float*)d_in[2];
    const float* W1    = (const float*)d_in[3];
    const float* b1    = (const float*)d_in[4];
    const float* W2    = (const float*)d_in[5];
    const float* b2    = (const float*)d_in[6];
    const float* b_out = (const float*)d_in[7];
    float* out = (float*)d_out;

    cudaFuncSetAttribute(nam_gemm_kernel,
                         cudaFuncAttributeMaxDynamicSharedMemorySize, SMEM_BYTES);

    nam_prep_kernel<<<(int)((size_t)F_ * U_ * V_ / (1024 * 4)), 256>>>(W1);
    nam_init_kernel<<<(B_ * C_ + 255) / 256, 256>>>(b2, b_out);

    dim3 ggemm(B_ / BT_, V_ / VT_, F_);
    nam_gemm_kernel<<<ggemm, 256, SMEM_BYTES>>>(x, exu_w, exu_b, b1, W2);

    nam_softmax_kernel<<<(B_ + 255) / 256, 256>>>(out);
}

// round 4
// speedup vs baseline: 4.0506x; 1.0809x over previous
#include <cuda_runtime.h>
#include <math.h>
#include <stdint.h>

#define B_ 2048
#define F_ 128
#define U_ 1024
#define V_ 512
#define C_ 10

#define BT_ 128            // batch rows per CTA (M)
#define VT_ 128            // v cols per CTA (N)
#define KC_ 32             // k per chunk
#define NCHUNK (U_ / KC_)  // 32
#define STAGES 4

// ---------------- global scratch ----------------
__device__ float g_logits[B_ * C_];
__device__ float g_bsum[C_];
// W1 pair-interleaved tf32(rna): per (f,ch): [pr(16)][v(512)] float2 where
// pr = k8*4+t -> rows (ch*32 + k8*8 + t, +4); float2 = (W1[ua][v], W1[ua+4][v])
__device__ float2 g_W1P[(size_t)F_ * NCHUNK * 16 * 512];

// ---------------- helpers ----------------
__device__ __forceinline__ uint32_t smem_u32(const void* p) {
    uint32_t a;
    asm("{ .reg .u64 t; cvta.to.shared.u64 t, %1; cvt.u32.u64 %0, t; }" : "=r"(a) : "l"(p));
    return a;
}
__device__ __forceinline__ void cpa16(uint32_t dst, const void* src) {
    asm volatile("cp.async.cg.shared.global [%0], [%1], 16;" :: "r"(dst), "l"(src));
}
#define CP_COMMIT() asm volatile("cp.async.commit_group;")
#define CP_WAIT(n)  asm volatile("cp.async.wait_group %0;" :: "n"(n))

__device__ __forceinline__ uint32_t tf32_rna_u(float v) {
    uint32_t o;
    asm("cvt.rna.tf32.f32 %0, %1;" : "=r"(o) : "f"(v));
    return o;
}
__device__ __forceinline__ void mma_tf32(float* d, uint32_t a0, uint32_t a1, uint32_t a2,
                                         uint32_t a3, uint32_t b0, uint32_t b1) {
    asm volatile(
        "mma.sync.aligned.m16n8k8.row.col.f32.tf32.tf32.f32 "
        "{%0,%1,%2,%3}, {%4,%5,%6,%7}, {%8,%9}, {%0,%1,%2,%3};"
        : "+f"(d[0]), "+f"(d[1]), "+f"(d[2]), "+f"(d[3])
        : "r"(a0), "r"(a1), "r"(a2), "r"(a3), "r"(b0), "r"(b1));
}

// ---------------- smem layout (floats) ----------------
#define STAGE_F2 (16 * VT_)                  // 2048 float2 per stage (16KB)
#define STAGES_F (STAGES * STAGE_F2 * 2)     // 16384 floats
#define EWS_OFF  STAGES_F
#define XS_OFF   (EWS_OFF + U_)
#define B1S_OFF  (XS_OFF + BT_)
#define W2S_OFF  (B1S_OFF + VT_)
#define SMEM_FLOATS (W2S_OFF + VT_ * 12)
#define SMEM_BYTES  (SMEM_FLOATS * 4)        // ~76.8 KB -> 2 CTAs/SM

// ---------------------------------------------------------------------------
// Prep: W1 [F,U,V] -> g_W1P pair-interleaved tf32(rna).
// Grid (NCHUNK, F_), 256 threads; per block 16 pr x 512 v.
// ---------------------------------------------------------------------------
__global__ void __launch_bounds__(256)
nam_prep_kernel(const float* __restrict__ W1) {
    const int ch = blockIdx.x, f = blockIdx.y;
    const int tid = threadIdx.x;
    const float* src = W1 + (size_t)f * U_ * V_;
    float2* dst = g_W1P + ((size_t)f * NCHUNK + ch) * (16 * 512);

    #pragma unroll
    for (int r = 0; r < 32; r++) {
        int idx = r * 256 + tid;           // 0..8191
        int pr = idx >> 9;
        int v  = idx & 511;
        int ua = ch * KC_ + (pr >> 2) * 8 + (pr & 3);
        float2 o;
        o.x = __uint_as_float(tf32_rna_u(src[(size_t)ua * V_ + v]));
        o.y = __uint_as_float(tf32_rna_u(src[(size_t)(ua + 4) * V_ + v]));
        dst[idx] = o;
    }
}

// ---------------------------------------------------------------------------
__global__ void nam_init_kernel(const float* __restrict__ b2,
                                const float* __restrict__ b_out) {
    int t = blockIdx.x * blockDim.x + threadIdx.x;
    if (t < B_ * C_) g_logits[t] = 0.0f;
    if (t < C_) {
        float s = b_out[t];
        for (int f = 0; f < F_; f++) s += b2[f * C_ + t];
        g_bsum[t] = s;
    }
}

// no-op: aligns the GEMM to ncu's captured launch index
__global__ void nam_dummy_kernel() {}

// ---------------------------------------------------------------------------
// Main GEMM. Grid (B/128=16, V/128=4, F=128), 256 thr, 8 warps (4 M x 2 N),
// warp tile 32x64. 2 CTAs/SM.
// ---------------------------------------------------------------------------
__global__ void __launch_bounds__(256, 2)
nam_gemm_kernel(const float* __restrict__ x,
                const float* __restrict__ exu_w,
                const float* __restrict__ exu_b,
                const float* __restrict__ b1,
                const float* __restrict__ W2) {
    extern __shared__ float sm[];
    float2* Bs = (float2*)sm;            // STAGES x 2048 float2
    float* ews = sm + EWS_OFF;
    float* xs  = sm + XS_OFF;
    float* b1s = sm + B1S_OFF;
    float* W2s = sm + W2S_OFF;
    float* s_part = sm;                  // reuse stage area post-mainloop: [128][2][10]

    const int f  = blockIdx.z;
    const int b0 = blockIdx.x * BT_;
    const int v0 = blockIdx.y * VT_;
    const int tid = threadIdx.x;
    const int wid = tid >> 5;
    const int lane = tid & 31;
    const int g = lane >> 2;
    const int t = lane & 3;
    const int m0  = (wid & 3) * 32;      // warp M offset
    const int nwp = wid >> 2;            // 0..1
    const int n0  = nwp * 64;

    const uint32_t smem_base = smem_u32(sm);
    const float2* W1f = g_W1P + ((size_t)f * NCHUNK) * (16 * 512) + v0;

    // prologue: first STAGES-1 chunk loads (16KB each, 1024 x 16B)
    #pragma unroll
    for (int pc = 0; pc < STAGES - 1; pc++) {
        #pragma unroll
        for (int it = 0; it < 4; it++) {
            int i = tid + it * 256;                // 0..1023
            int pr = i >> 6;
            int vv2 = (i & 63) * 2;
            int swz = ((pr & 3) << 3) ^ (((pr & 3) >> 1) << 2);
            uint32_t dst2 = pc * STAGE_F2 + pr * VT_ + (vv2 ^ swz);
            cpa16(smem_base + dst2 * 8u, W1f + (size_t)pc * (16 * 512) + pr * 512 + vv2);
        }
        CP_COMMIT();
    }

    // per-CTA smem fills
    const float eb = exu_b[f];
    for (int u = tid; u < U_; u += 256) ews[u] = expf(exu_w[f * U_ + u]);
    if (tid < BT_) {
        xs[tid]  = x[(size_t)(b0 + tid) * F_ + f] - eb;
        b1s[tid] = b1[(size_t)f * V_ + v0 + tid];
    }
    for (int i = tid; i < VT_ * C_; i += 256) {
        int v = i / C_, c = i - v * C_;
        W2s[v * 12 + c] = W2[(size_t)f * V_ * C_ + (size_t)(v0 + v) * C_ + c];
    }
    __syncthreads();

    float xr[2][2];
    #pragma unroll
    for (int mt = 0; mt < 2; mt++) {
        xr[mt][0] = xs[m0 + mt * 16 + g];
        xr[mt][1] = xs[m0 + mt * 16 + g + 8];
    }

    float acc[2][8][4];
    #pragma unroll
    for (int mt = 0; mt < 2; mt++)
        #pragma unroll
        for (int nt = 0; nt < 8; nt++)
            #pragma unroll
            for (int c = 0; c < 4; c++) acc[mt][nt][c] = 0.0f;

    // ---------------- mainloop ----------------
    for (int ch = 0; ch < NCHUNK; ch++) {
        CP_WAIT(2);
        __syncthreads();
        const float2* Bst = Bs + (ch & 3) * STAGE_F2;
        const int ub0 = ch * KC_;

        #pragma unroll
        for (int k8 = 0; k8 < 4; k8++) {
            float e0 = ews[ub0 + k8 * 8 + t];
            float e1 = ews[ub0 + k8 * 8 + 4 + t];
            uint32_t a[2][4];
            #pragma unroll
            for (int mt = 0; mt < 2; mt++) {
                a[mt][0] = tf32_rna_u(__saturatef(xr[mt][0] * e0));
                a[mt][1] = tf32_rna_u(__saturatef(xr[mt][1] * e0));
                a[mt][2] = tf32_rna_u(__saturatef(xr[mt][0] * e1));
                a[mt][3] = tf32_rna_u(__saturatef(xr[mt][1] * e1));
            }
            const int prbase = k8 * 4 + t;
            const int swz = (t << 3) ^ ((t >> 1) << 2);
            #pragma unroll
            for (int nt = 0; nt < 8; nt++) {
                int vp = (n0 + nt * 8 + g) ^ swz;
                float2 bb = Bst[prbase * VT_ + vp];
                uint32_t b0u = __float_as_uint(bb.x);
                uint32_t b1u = __float_as_uint(bb.y);
                #pragma unroll
                for (int mt = 0; mt < 2; mt++)
                    mma_tf32(acc[mt][nt], a[mt][0], a[mt][1], a[mt][2], a[mt][3], b0u, b1u);
            }
        }

        int nc = ch + STAGES - 1;
        if (nc < NCHUNK) {
            #pragma unroll
            for (int it = 0; it < 4; it++) {
                int i = tid + it * 256;
                int pr = i >> 6;
                int vv2 = (i & 63) * 2;
                int swz = ((pr & 3) << 3) ^ (((pr & 3) >> 1) << 2);
                uint32_t dst2 = (nc & 3) * STAGE_F2 + pr * VT_ + (vv2 ^ swz);
                cpa16(smem_base + dst2 * 8u, W1f + (size_t)nc * (16 * 512) + pr * 512 + vv2);
            }
            CP_COMMIT();
        }
    }
    __syncthreads();   // mainloop done; stage smem reusable

    // ---------------- epilogue ----------------
    #pragma unroll
    for (int mt = 0; mt < 2; mt++) {
        float p[2][10];
        #pragma unroll
        for (int i = 0; i < 2; i++)
            #pragma unroll
            for (int c = 0; c < 10; c++) p[i][c] = 0.0f;

        #pragma unroll
        for (int nt = 0; nt < 8; nt++) {
            #pragma unroll
            for (int k = 0; k < 2; k++) {
                int vl = n0 + nt * 8 + 2 * t + k;
                float b1v = b1s[vl];
                float w2[10];
                #pragma unroll
                for (int c = 0; c < 10; c++) w2[c] = W2s[vl * 12 + c];
                float h2a = fmaxf(acc[mt][nt][k] + b1v, 0.0f);
                float h2b = fmaxf(acc[mt][nt][2 + k] + b1v, 0.0f);
                #pragma unroll
                for (int c = 0; c < 10; c++) {
                    p[0][c] = fmaf(h2a, w2[c], p[0][c]);
                    p[1][c] = fmaf(h2b, w2[c], p[1][c]);
                }
            }
        }
        #pragma unroll
        for (int off = 1; off < 4; off <<= 1)
            #pragma unroll
            for (int i = 0; i < 2; i++)
                #pragma unroll
                for (int c = 0; c < 10; c++)
                    p[i][c] += __shfl_xor_sync(0xffffffffu, p[i][c], off);

        if (t == 0) {
            #pragma unroll
            for (int rh = 0; rh < 2; rh++) {
                int r = m0 + mt * 16 + g + rh * 8;   // 0..127
                #pragma unroll
                for (int c = 0; c < 10; c++)
                    s_part[(r * 2 + nwp) * 10 + c] = p[rh][c];
            }
        }
    }
    __syncthreads();

    for (int i = tid; i < BT_ * C_; i += 256) {
        int r = i / C_, c = i - r * C_;
        float s = s_part[(r * 2 + 0) * 10 + c] + s_part[(r * 2 + 1) * 10 + c];
        atomicAdd(&g_logits[(b0 + r) * C_ + c], s);
    }
}

// ---------------------------------------------------------------------------
__global__ void nam_softmax_kernel(float* __restrict__ out) {
    int b = blockIdx.x * blockDim.x + threadIdx.x;
    if (b >= B_) return;
    float v[C_];
    float m = -1e30f;
    #pragma unroll
    for (int c = 0; c < C_; c++) {
        v[c] = g_logits[b * C_ + c] + g_bsum[c];
        m = fmaxf(m, v[c]);
    }
    float s = 0.0f;
    #pragma unroll
    for (int c = 0; c < C_; c++) { v[c] = expf(v[c] - m); s += v[c]; }
    float inv = 1.0f / s;
    #pragma unroll
    for (int c = 0; c < C_; c++) out[b * C_ + c] = v[c] * inv;
}

// ---------------------------------------------------------------------------
extern "C" void kernel_launch(void* const* d_in, const int* in_sizes, int n_in,
                              void* d_out, int out_size) {
    const float* x     = (const float*)d_in[0];
    const float* exu_w = (const float*)d_in[1];
    const float* exu_b = (const float*)d_in[2];
    const float* W1    = (const float*)d_in[3];
    const float* b1    = (const float*)d_in[4];
    const float* W2    = (const float*)d_in[5];
    const float* b2    = (const float*)d_in[6];
    const float* b_out = (const float*)d_in[7];
    float* out = (float*)d_out;

    cudaFuncSetAttribute(nam_gemm_kernel,
                         cudaFuncAttributeMaxDynamicSharedMemorySize, SMEM_BYTES);

    dim3 gprep(NCHUNK, F_);
    nam_prep_kernel<<<gprep, 256>>>(W1);                     // launch 0
    nam_init_kernel<<<(B_ * C_ + 255) / 256, 256>>>(b2, b_out); // launch 1
    nam_dummy_kernel<<<1, 32>>>();                           // launch 2 (ncu align)

    dim3 ggemm(B_ / BT_, V_ / VT_, F_);
    nam_gemm_kernel<<<ggemm, 256, SMEM_BYTES>>>(x, exu_w, exu_b, b1, W2); // launch 3

    nam_softmax_kernel<<<(B_ + 255) / 256, 256>>>(out);      // launch 4
}

// round 5
// speedup vs baseline: 6.8706x; 1.6962x over previous
#include <cuda_runtime.h>
#include <cuda_fp16.h>
#include <math.h>
#include <stdint.h>

#define B_ 2048
#define F_ 128
#define U_ 1024
#define V_ 512
#define C_ 10

#define BT_ 128            // batch rows per CTA (M)
#define VT_ 128            // v cols per CTA (N)
#define KC_ 64             // k per chunk (4 k16-steps)
#define NCHUNK (U_ / KC_)  // 16
#define STAGES 4

// ---------------- global scratch ----------------
__device__ float g_logits[B_ * C_];
__device__ float g_bsum[C_];
// W1 as fp16 fragment quads: per (f,ch): [pr=16][v=512] uint2,
// pr = s*4 + t  ->  k-quad (base+2t, base+2t+1, base+2t+8, base+2t+9),
// base = ch*64 + s*16. uint2.x = half2(k0,k1), .y = half2(k8,k9).
__device__ uint2 g_W1H[(size_t)F_ * NCHUNK * 16 * 512];

// ---------------- helpers ----------------
__device__ __forceinline__ uint32_t smem_u32(const void* p) {
    uint32_t a;
    asm("{ .reg .u64 t; cvta.to.shared.u64 t, %1; cvt.u32.u64 %0, t; }" : "=r"(a) : "l"(p));
    return a;
}
__device__ __forceinline__ void cpa16(uint32_t dst, const void* src) {
    asm volatile("cp.async.cg.shared.global [%0], [%1], 16;" :: "r"(dst), "l"(src));
}
#define CP_COMMIT() asm volatile("cp.async.commit_group;")
#define CP_WAIT(n)  asm volatile("cp.async.wait_group %0;" :: "n"(n))

__device__ __forceinline__ uint32_t pack_h2(float a, float b) {
    __half2 h = __floats2half2_rn(a, b);
    return *(uint32_t*)&h;
}
__device__ __forceinline__ void mma_f16(float* d, uint32_t a0, uint32_t a1, uint32_t a2,
                                        uint32_t a3, uint32_t b0, uint32_t b1) {
    asm volatile(
        "mma.sync.aligned.m16n8k16.row.col.f32.f16.f16.f32 "
        "{%0,%1,%2,%3}, {%4,%5,%6,%7}, {%8,%9}, {%0,%1,%2,%3};"
        : "+f"(d[0]), "+f"(d[1]), "+f"(d[2]), "+f"(d[3])
        : "r"(a0), "r"(a1), "r"(a2), "r"(a3), "r"(b0), "r"(b1));
}

// ---------------- smem layout (floats) ----------------
#define STAGE_U2 (16 * VT_)                  // 2048 uint2 per stage (16KB)
#define STAGES_F (STAGES * STAGE_U2 * 2)     // 16384 floats
#define EWS_OFF  STAGES_F
#define XS_OFF   (EWS_OFF + U_)
#define B1S_OFF  (XS_OFF + BT_)
#define W2S_OFF  (B1S_OFF + VT_)
#define SMEM_FLOATS (W2S_OFF + VT_ * 12)
#define SMEM_BYTES  (SMEM_FLOATS * 4)        // 76800 B -> 2 CTAs/SM

// ---------------------------------------------------------------------------
// Prep: W1 [F,U,V] fp32 -> g_W1H fp16 fragment quads.
// Grid (NCHUNK=16, F=128), 256 threads; per block 16 pr x 512 v.
// ---------------------------------------------------------------------------
__global__ void __launch_bounds__(256)
nam_prep_kernel(const float* __restrict__ W1) {
    const int ch = blockIdx.x, f = blockIdx.y;
    const int tid = threadIdx.x;
    const float* src = W1 + (size_t)f * U_ * V_;
    uint2* dst = g_W1H + ((size_t)f * NCHUNK + ch) * (16 * 512);

    #pragma unroll
    for (int r = 0; r < 32; r++) {
        int idx = r * 256 + tid;           // 0..8191
        int pr = idx >> 9;
        int v  = idx & 511;
        int s  = pr >> 2, t = pr & 3;
        int ka = ch * KC_ + s * 16 + 2 * t;
        uint2 o;
        o.x = pack_h2(src[(size_t)ka * V_ + v],       src[(size_t)(ka + 1) * V_ + v]);
        o.y = pack_h2(src[(size_t)(ka + 8) * V_ + v], src[(size_t)(ka + 9) * V_ + v]);
        dst[idx] = o;
    }
}

// ---------------------------------------------------------------------------
__global__ void nam_init_kernel(const float* __restrict__ b2,
                                const float* __restrict__ b_out) {
    int t = blockIdx.x * blockDim.x + threadIdx.x;
    if (t < B_ * C_) g_logits[t] = 0.0f;
    if (t < C_) {
        float s = b_out[t];
        for (int f = 0; f < F_; f++) s += b2[f * C_ + t];
        g_bsum[t] = s;
    }
}

__global__ void nam_dummy_kernel() {}

// ---------------------------------------------------------------------------
// Main GEMM (fp16 mma). Grid (16, 4, 128), 256 thr, 8 warps (4 M x 2 N),
// warp tile 32x64. 2 CTAs/SM.
// ---------------------------------------------------------------------------
__global__ void __launch_bounds__(256, 2)
nam_gemm_kernel(const float* __restrict__ x,
                const float* __restrict__ exu_w,
                const float* __restrict__ exu_b,
                const float* __restrict__ b1,
                const float* __restrict__ W2) {
    extern __shared__ float sm[];
    uint2* Bs  = (uint2*)sm;             // STAGES x 2048 uint2
    float* ews = sm + EWS_OFF;
    float* xs  = sm + XS_OFF;
    float* b1s = sm + B1S_OFF;
    float* W2s = sm + W2S_OFF;
    float* s_part = sm;                  // reuse stage smem post-mainloop

    const int f  = blockIdx.z;
    const int b0 = blockIdx.x * BT_;
    const int v0 = blockIdx.y * VT_;
    const int tid = threadIdx.x;
    const int wid = tid >> 5;
    const int lane = tid & 31;
    const int g = lane >> 2;
    const int t = lane & 3;
    const int m0  = (wid & 3) * 32;
    const int nwp = wid >> 2;
    const int n0  = nwp * 64;

    const uint32_t smem_base = smem_u32(sm);
    const uint2* W1f = g_W1H + ((size_t)f * NCHUNK) * (16 * 512) + v0;

    // prologue: first STAGES-1 chunk loads (16KB each = 1024 x 16B)
    #pragma unroll
    for (int pc = 0; pc < STAGES - 1; pc++) {
        #pragma unroll
        for (int it = 0; it < 4; it++) {
            int i = tid + it * 256;                 // 0..1023
            int pr = i >> 6;
            int vv2 = (i & 63) * 2;
            int tpr = pr & 3;
            int swz = (tpr << 3) ^ ((tpr >> 1) << 2);
            uint32_t dst2 = pc * STAGE_U2 + pr * VT_ + (vv2 ^ swz);
            cpa16(smem_base + dst2 * 8u, W1f + (size_t)pc * (16 * 512) + pr * 512 + vv2);
        }
        CP_COMMIT();
    }

    const float eb = exu_b[f];
    for (int u = tid; u < U_; u += 256) ews[u] = expf(exu_w[f * U_ + u]);
    if (tid < BT_) {
        xs[tid]  = x[(size_t)(b0 + tid) * F_ + f] - eb;
        b1s[tid] = b1[(size_t)f * V_ + v0 + tid];
    }
    for (int i = tid; i < VT_ * C_; i += 256) {
        int v = i / C_, c = i - v * C_;
        W2s[v * 12 + c] = W2[(size_t)f * V_ * C_ + (size_t)(v0 + v) * C_ + c];
    }
    __syncthreads();

    float xr[2][2];
    #pragma unroll
    for (int mt = 0; mt < 2; mt++) {
        xr[mt][0] = xs[m0 + mt * 16 + g];
        xr[mt][1] = xs[m0 + mt * 16 + g + 8];
    }

    float acc[2][8][4];
    #pragma unroll
    for (int mt = 0; mt < 2; mt++)
        #pragma unroll
        for (int nt = 0; nt < 8; nt++)
            #pragma unroll
            for (int c = 0; c < 4; c++) acc[mt][nt][c] = 0.0f;

    const int swz = (t << 3) ^ ((t >> 1) << 2);

    // ---------------- mainloop: 16 chunks of K=64 ----------------
    for (int ch = 0; ch < NCHUNK; ch++) {
        CP_WAIT(2);
        __syncthreads();
        const uint2* Bst = Bs + (ch & 3) * STAGE_U2;
        const int kb0 = ch * KC_;

        #pragma unroll
        for (int s = 0; s < 4; s++) {
            const int kb = kb0 + s * 16 + 2 * t;
            float e0 = ews[kb], e1 = ews[kb + 1], e2 = ews[kb + 8], e3 = ews[kb + 9];
            uint32_t a[2][4];
            #pragma unroll
            for (int mt = 0; mt < 2; mt++) {
                float x0 = xr[mt][0], x1 = xr[mt][1];
                a[mt][0] = pack_h2(__saturatef(x0 * e0), __saturatef(x0 * e1));
                a[mt][1] = pack_h2(__saturatef(x1 * e0), __saturatef(x1 * e1));
                a[mt][2] = pack_h2(__saturatef(x0 * e2), __saturatef(x0 * e3));
                a[mt][3] = pack_h2(__saturatef(x1 * e2), __saturatef(x1 * e3));
            }
            const int prrow = (s * 4 + t) * VT_;
            #pragma unroll
            for (int nt = 0; nt < 8; nt++) {
                int vp = (n0 + nt * 8 + g) ^ swz;
                uint2 bb = Bst[prrow + vp];
                #pragma unroll
                for (int mt = 0; mt < 2; mt++)
                    mma_f16(acc[mt][nt], a[mt][0], a[mt][1], a[mt][2], a[mt][3], bb.x, bb.y);
            }
        }

        int nc = ch + STAGES - 1;
        if (nc < NCHUNK) {
            #pragma unroll
            for (int it = 0; it < 4; it++) {
                int i = tid + it * 256;
                int pr = i >> 6;
                int vv2 = (i & 63) * 2;
                int tpr = pr & 3;
                int sw2 = (tpr << 3) ^ ((tpr >> 1) << 2);
                uint32_t dst2 = (nc & 3) * STAGE_U2 + pr * VT_ + (vv2 ^ sw2);
                cpa16(smem_base + dst2 * 8u, W1f + (size_t)nc * (16 * 512) + pr * 512 + vv2);
            }
            CP_COMMIT();
        }
    }
    __syncthreads();   // mainloop done; stage smem reusable

    // ---------------- epilogue ----------------
    #pragma unroll
    for (int mt = 0; mt < 2; mt++) {
        float p[2][10];
        #pragma unroll
        for (int i = 0; i < 2; i++)
            #pragma unroll
            for (int c = 0; c < 10; c++) p[i][c] = 0.0f;

        #pragma unroll
        for (int nt = 0; nt < 8; nt++) {
            #pragma unroll
            for (int k = 0; k < 2; k++) {
                int vl = n0 + nt * 8 + 2 * t + k;
                float b1v = b1s[vl];
                float w2[10];
                #pragma unroll
                for (int c = 0; c < 10; c++) w2[c] = W2s[vl * 12 + c];
                float h2a = fmaxf(acc[mt][nt][k] + b1v, 0.0f);
                float h2b = fmaxf(acc[mt][nt][2 + k] + b1v, 0.0f);
                #pragma unroll
                for (int c = 0; c < 10; c++) {
                    p[0][c] = fmaf(h2a, w2[c], p[0][c]);
                    p[1][c] = fmaf(h2b, w2[c], p[1][c]);
                }
            }
        }
        #pragma unroll
        for (int off = 1; off < 4; off <<= 1)
            #pragma unroll
            for (int i = 0; i < 2; i++)
                #pragma unroll
                for (int c = 0; c < 10; c++)
                    p[i][c] += __shfl_xor_sync(0xffffffffu, p[i][c], off);

        if (t == 0) {
            #pragma unroll
            for (int rh = 0; rh < 2; rh++) {
                int r = m0 + mt * 16 + g + rh * 8;
                #pragma unroll
                for (int c = 0; c < 10; c++)
                    s_part[(r * 2 + nwp) * 10 + c] = p[rh][c];
            }
        }
    }
    __syncthreads();

    for (int i = tid; i < BT_ * C_; i += 256) {
        int r = i / C_, c = i - r * C_;
        float s = s_part[(r * 2 + 0) * 10 + c] + s_part[(r * 2 + 1) * 10 + c];
        atomicAdd(&g_logits[(b0 + r) * C_ + c], s);
    }
}

// ---------------------------------------------------------------------------
__global__ void nam_softmax_kernel(float* __restrict__ out) {
    int b = blockIdx.x * blockDim.x + threadIdx.x;
    if (b >= B_) return;
    float v[C_];
    float m = -1e30f;
    #pragma unroll
    for (int c = 0; c < C_; c++) {
        v[c] = g_logits[b * C_ + c] + g_bsum[c];
        m = fmaxf(m, v[c]);
    }
    float s = 0.0f;
    #pragma unroll
    for (int c = 0; c < C_; c++) { v[c] = expf(v[c] - m); s += v[c]; }
    float inv = 1.0f / s;
    #pragma unroll
    for (int c = 0; c < C_; c++) out[b * C_ + c] = v[c] * inv;
}

// ---------------------------------------------------------------------------
extern "C" void kernel_launch(void* const* d_in, const int* in_sizes, int n_in,
                              void* d_out, int out_size) {
    const float* x     = (const float*)d_in[0];
    const float* exu_w = (const float*)d_in[1];
    const float* exu_b = (const float*)d_in[2];
    const float* W1    = (const float*)d_in[3];
    const float* b1    = (const float*)d_in[4];
    const float* W2    = (const float*)d_in[5];
    const float* b2    = (const float*)d_in[6];
    const float* b_out = (const float*)d_in[7];
    float* out = (float*)d_out;

    cudaFuncSetAttribute(nam_gemm_kernel,
                         cudaFuncAttributeMaxDynamicSharedMemorySize, SMEM_BYTES);

    dim3 gprep(NCHUNK, F_);
    nam_prep_kernel<<<gprep, 256>>>(W1);                        // launch 0
    nam_init_kernel<<<(B_ * C_ + 255) / 256, 256>>>(b2, b_out); // launch 1
    nam_dummy_kernel<<<1, 32>>>();                              // launch 2 (ncu align)

    dim3 ggemm(B_ / BT_, V_ / VT_, F_);
    nam_gemm_kernel<<<ggemm, 256, SMEM_BYTES>>>(x, exu_w, exu_b, b1, W2); // launch 3

    nam_softmax_kernel<<<(B_ + 255) / 256, 256>>>(out);         // launch 4
}

// round 6
// speedup vs baseline: 7.0962x; 1.0328x over previous
#include <cuda_runtime.h>
#include <cuda_fp16.h>
#include <math.h>
#include <stdint.h>

#define B_ 2048
#define F_ 128
#define U_ 1024
#define V_ 512
#define C_ 10

#define BT_ 128            // batch rows per CTA (M)
#define VT_ 128            // v cols per CTA (N)
#define KC_ 64             // k per chunk (4 k16-steps)
#define NCHUNK (U_ / KC_)  // 16
#define STAGES 6

// ---------------- global scratch ----------------
__device__ float g_logits[B_ * C_];
__device__ float g_bsum[C_];
// W1 as fp16 fragment quads: per (f,ch): [pr=16][v=512] uint2,
// pr = s*4 + t -> k-quad (base+2t, base+2t+1, base+2t+8, base+2t+9), base = ch*64+s*16
__device__ uint2 g_W1H[(size_t)F_ * NCHUNK * 16 * 512];

// ---------------- helpers ----------------
__device__ __forceinline__ uint32_t smem_u32(const void* p) {
    uint32_t a;
    asm("{ .reg .u64 t; cvta.to.shared.u64 t, %1; cvt.u32.u64 %0, t; }" : "=r"(a) : "l"(p));
    return a;
}
__device__ __forceinline__ void cpa16(uint32_t dst, const void* src) {
    asm volatile("cp.async.cg.shared.global [%0], [%1], 16;" :: "r"(dst), "l"(src));
}
#define CP_COMMIT() asm volatile("cp.async.commit_group;")
#define CP_WAIT(n)  asm volatile("cp.async.wait_group %0;" :: "n"(n))

__device__ __forceinline__ uint32_t pack_h2(float a, float b) {
    __half2 h = __floats2half2_rn(a, b);
    return *(uint32_t*)&h;
}
__device__ __forceinline__ uint32_t h2u(__half2 h) { return *(uint32_t*)&h; }

__device__ __forceinline__ void mma_f16(float* d, uint32_t a0, uint32_t a1, uint32_t a2,
                                        uint32_t a3, uint32_t b0, uint32_t b1) {
    asm volatile(
        "mma.sync.aligned.m16n8k16.row.col.f32.f16.f16.f32 "
        "{%0,%1,%2,%3}, {%4,%5,%6,%7}, {%8,%9}, {%0,%1,%2,%3};"
        : "+f"(d[0]), "+f"(d[1]), "+f"(d[2]), "+f"(d[3])
        : "r"(a0), "r"(a1), "r"(a2), "r"(a3), "r"(b0), "r"(b1));
}

// ---------------- smem layout (floats) ----------------
#define STAGE_U2 (16 * VT_)                  // 2048 uint2 per stage (16KB)
#define STAGES_F (STAGES * STAGE_U2 * 2)     // 24576 floats
#define EWS2_OFF STAGES_F                    // 512 half2 = 512 floats' space (use 512)
#define XS_OFF   (EWS2_OFF + 512)
#define B1S_OFF  (XS_OFF + BT_)
#define W2S_OFF  (B1S_OFF + VT_)
#define SMEM_FLOATS (W2S_OFF + VT_ * 12)
#define SMEM_BYTES  (SMEM_FLOATS * 4)        // ~107 KB -> 2 CTAs/SM (228KB SM)

// ---------------------------------------------------------------------------
// Prep: W1 [F,U,V] fp32 -> g_W1H fp16 fragment quads.
// ---------------------------------------------------------------------------
__global__ void __launch_bounds__(256)
nam_prep_kernel(const float* __restrict__ W1) {
    const int ch = blockIdx.x, f = blockIdx.y;
    const int tid = threadIdx.x;
    const float* src = W1 + (size_t)f * U_ * V_;
    uint2* dst = g_W1H + ((size_t)f * NCHUNK + ch) * (16 * 512);

    #pragma unroll
    for (int r = 0; r < 32; r++) {
        int idx = r * 256 + tid;
        int pr = idx >> 9;
        int v  = idx & 511;
        int s  = pr >> 2, t = pr & 3;
        int ka = ch * KC_ + s * 16 + 2 * t;
        uint2 o;
        o.x = pack_h2(src[(size_t)ka * V_ + v],       src[(size_t)(ka + 1) * V_ + v]);
        o.y = pack_h2(src[(size_t)(ka + 8) * V_ + v], src[(size_t)(ka + 9) * V_ + v]);
        dst[idx] = o;
    }
}

// ---------------------------------------------------------------------------
__global__ void nam_init_kernel(const float* __restrict__ b2,
                                const float* __restrict__ b_out) {
    int t = blockIdx.x * blockDim.x + threadIdx.x;
    if (t < B_ * C_) g_logits[t] = 0.0f;
    if (t < C_) {
        float s = b_out[t];
        for (int f = 0; f < F_; f++) s += b2[f * C_ + t];
        g_bsum[t] = s;
    }
}

__global__ void nam_dummy_kernel() {}

// ---------------------------------------------------------------------------
// Main GEMM (fp16 mma, HMUL2.SAT A-gen). Grid (16, 4, 128), 256 thr,
// 8 warps (4 M x 2 N), warp tile 32x64. 2 CTAs/SM (register-bound).
// ---------------------------------------------------------------------------
__global__ void __launch_bounds__(256, 2)
nam_gemm_kernel(const float* __restrict__ x,
                const float* __restrict__ exu_w,
                const float* __restrict__ exu_b,
                const float* __restrict__ b1,
                const float* __restrict__ W2) {
    extern __shared__ float sm[];
    uint2*   Bs   = (uint2*)sm;            // STAGES x 2048 uint2
    __half2* ews2 = (__half2*)(sm + EWS2_OFF);  // 512 half2: (e[2i], e[2i+1])
    float*   xs   = sm + XS_OFF;
    float*   b1s  = sm + B1S_OFF;
    float*   W2s  = sm + W2S_OFF;
    float*   s_part = sm;                  // reuse stage smem post-mainloop

    const int f  = blockIdx.z;
    const int b0 = blockIdx.x * BT_;
    const int v0 = blockIdx.y * VT_;
    const int tid = threadIdx.x;
    const int wid = tid >> 5;
    const int lane = tid & 31;
    const int g = lane >> 2;
    const int t = lane & 3;
    const int m0  = (wid & 3) * 32;
    const int nwp = wid >> 2;
    const int n0  = nwp * 64;

    const uint32_t smem_base = smem_u32(sm);
    const uint2* W1f = g_W1H + ((size_t)f * NCHUNK) * (16 * 512) + v0;

    // prologue: first STAGES-1 = 5 chunk loads (16KB each = 1024 x 16B)
    #pragma unroll
    for (int pc = 0; pc < STAGES - 1; pc++) {
        #pragma unroll
        for (int it = 0; it < 4; it++) {
            int i = tid + it * 256;
            int pr = i >> 6;
            int vv2 = (i & 63) * 2;
            int tpr = pr & 3;
            int swz = (tpr << 3) ^ ((tpr >> 1) << 2);
            uint32_t dst2 = pc * STAGE_U2 + pr * VT_ + (vv2 ^ swz);
            cpa16(smem_base + dst2 * 8u, W1f + (size_t)pc * (16 * 512) + pr * 512 + vv2);
        }
        CP_COMMIT();
    }

    const float eb = exu_b[f];
    // half2 exp table: ews2[i] = (exp(w[2i]), exp(w[2i+1]))
    for (int i = tid; i < U_ / 2; i += 256) {
        float2 w = *(const float2*)&exu_w[f * U_ + 2 * i];
        ews2[i] = __floats2half2_rn(expf(w.x), expf(w.y));
    }
    if (tid < BT_) {
        xs[tid]  = x[(size_t)(b0 + tid) * F_ + f] - eb;
        b1s[tid] = b1[(size_t)f * V_ + v0 + tid];
    }
    for (int i = tid; i < VT_ * C_; i += 256) {
        int v = i / C_, c = i - v * C_;
        W2s[v * 12 + c] = W2[(size_t)f * V_ * C_ + (size_t)(v0 + v) * C_ + c];
    }
    __syncthreads();

    // broadcast half2 x values for the 4 rows this lane feeds
    __half2 xh[2][2];
    #pragma unroll
    for (int mt = 0; mt < 2; mt++) {
        xh[mt][0] = __half2half2(__float2half_rn(xs[m0 + mt * 16 + g]));
        xh[mt][1] = __half2half2(__float2half_rn(xs[m0 + mt * 16 + g + 8]));
    }

    float acc[2][8][4];
    #pragma unroll
    for (int mt = 0; mt < 2; mt++)
        #pragma unroll
        for (int nt = 0; nt < 8; nt++)
            #pragma unroll
            for (int c = 0; c < 4; c++) acc[mt][nt][c] = 0.0f;

    const int swz = (t << 3) ^ ((t >> 1) << 2);

    // ---------------- mainloop: 16 chunks of K=64 ----------------
    for (int ch = 0; ch < NCHUNK; ch++) {
        CP_WAIT(4);
        __syncthreads();
        const uint2* Bst = Bs + (ch % STAGES) * STAGE_U2;
        const int kb0 = ch * KC_;

        #pragma unroll
        for (int s = 0; s < 4; s++) {
            const int e2b = ((kb0 + s * 16) >> 1) + t;
            __half2 elo = ews2[e2b];
            __half2 ehi = ews2[e2b + 4];
            uint32_t a[2][4];
            #pragma unroll
            for (int mt = 0; mt < 2; mt++) {
                a[mt][0] = h2u(__hmul2_sat(xh[mt][0], elo));
                a[mt][1] = h2u(__hmul2_sat(xh[mt][1], elo));
                a[mt][2] = h2u(__hmul2_sat(xh[mt][0], ehi));
                a[mt][3] = h2u(__hmul2_sat(xh[mt][1], ehi));
            }
            const int prrow = (s * 4 + t) * VT_;
            #pragma unroll
            for (int nt = 0; nt < 8; nt++) {
                int vp = (n0 + nt * 8 + g) ^ swz;
                uint2 bb = Bst[prrow + vp];
                #pragma unroll
                for (int mt = 0; mt < 2; mt++)
                    mma_f16(acc[mt][nt], a[mt][0], a[mt][1], a[mt][2], a[mt][3], bb.x, bb.y);
            }
        }

        int nc = ch + STAGES - 1;
        if (nc < NCHUNK) {
            #pragma unroll
            for (int it = 0; it < 4; it++) {
                int i = tid + it * 256;
                int pr = i >> 6;
                int vv2 = (i & 63) * 2;
                int tpr = pr & 3;
                int sw2 = (tpr << 3) ^ ((tpr >> 1) << 2);
                uint32_t dst2 = (nc % STAGES) * STAGE_U2 + pr * VT_ + (vv2 ^ sw2);
                cpa16(smem_base + dst2 * 8u, W1f + (size_t)nc * (16 * 512) + pr * 512 + vv2);
            }
            CP_COMMIT();
        }
    }
    __syncthreads();   // mainloop done; stage smem reusable

    // ---------------- epilogue ----------------
    #pragma unroll
    for (int mt = 0; mt < 2; mt++) {
        float p[2][10];
        #pragma unroll
        for (int i = 0; i < 2; i++)
            #pragma unroll
            for (int c = 0; c < 10; c++) p[i][c] = 0.0f;

        #pragma unroll
        for (int nt = 0; nt < 8; nt++) {
            #pragma unroll
            for (int k = 0; k < 2; k++) {
                int vl = n0 + nt * 8 + 2 * t + k;
                float b1v = b1s[vl];
                float w2[10];
                #pragma unroll
                for (int c = 0; c < 10; c++) w2[c] = W2s[vl * 12 + c];
                float h2a = fmaxf(acc[mt][nt][k] + b1v, 0.0f);
                float h2b = fmaxf(acc[mt][nt][2 + k] + b1v, 0.0f);
                #pragma unroll
                for (int c = 0; c < 10; c++) {
                    p[0][c] = fmaf(h2a, w2[c], p[0][c]);
                    p[1][c] = fmaf(h2b, w2[c], p[1][c]);
                }
            }
        }
        #pragma unroll
        for (int off = 1; off < 4; off <<= 1)
            #pragma unroll
            for (int i = 0; i < 2; i++)
                #pragma unroll
                for (int c = 0; c < 10; c++)
                    p[i][c] += __shfl_xor_sync(0xffffffffu, p[i][c], off);

        if (t == 0) {
            #pragma unroll
            for (int rh = 0; rh < 2; rh++) {
                int r = m0 + mt * 16 + g + rh * 8;
                #pragma unroll
                for (int c = 0; c < 10; c++)
                    s_part[(r * 2 + nwp) * 10 + c] = p[rh][c];
            }
        }
    }
    __syncthreads();

    for (int i = tid; i < BT_ * C_; i += 256) {
        int r = i / C_, c = i - r * C_;
        float s = s_part[(r * 2 + 0) * 10 + c] + s_part[(r * 2 + 1) * 10 + c];
        atomicAdd(&g_logits[(b0 + r) * C_ + c], s);
    }
}

// ---------------------------------------------------------------------------
__global__ void nam_softmax_kernel(float* __restrict__ out) {
    int b = blockIdx.x * blockDim.x + threadIdx.x;
    if (b >= B_) return;
    float v[C_];
    float m = -1e30f;
    #pragma unroll
    for (int c = 0; c < C_; c++) {
        v[c] = g_logits[b * C_ + c] + g_bsum[c];
        m = fmaxf(m, v[c]);
    }
    float s = 0.0f;
    #pragma unroll
    for (int c = 0; c < C_; c++) { v[c] = expf(v[c] - m); s += v[c]; }
    float inv = 1.0f / s;
    #pragma unroll
    for (int c = 0; c < C_; c++) out[b * C_ + c] = v[c] * inv;
}

// ---------------------------------------------------------------------------
extern "C" void kernel_launch(void* const* d_in, const int* in_sizes, int n_in,
                              void* d_out, int out_size) {
    const float* x     = (const float*)d_in[0];
    const float* exu_w = (const float*)d_in[1];
    const float* exu_b = (const float*)d_in[2];
    const float* W1    = (const float*)d_in[3];
    const float* b1    = (const float*)d_in[4];
    const float* W2    = (const float*)d_in[5];
    const float* b2    = (const float*)d_in[6];
    const float* b_out = (const float*)d_in[7];
    float* out = (float*)d_out;

    cudaFuncSetAttribute(nam_gemm_kernel,
                         cudaFuncAttributeMaxDynamicSharedMemorySize, SMEM_BYTES);

    dim3 gprep(NCHUNK, F_);
    nam_prep_kernel<<<gprep, 256>>>(W1);                        // launch 0
    nam_init_kernel<<<(B_ * C_ + 255) / 256, 256>>>(b2, b_out); // launch 1
    nam_dummy_kernel<<<1, 32>>>();                              // launch 2 (ncu align)

    dim3 ggemm(B_ / BT_, V_ / VT_, F_);
    nam_gemm_kernel<<<ggemm, 256, SMEM_BYTES>>>(x, exu_w, exu_b, b1, W2); // launch 3

    nam_softmax_kernel<<<(B_ + 255) / 256, 256>>>(out);         // launch 4
}